// round 2
// baseline (speedup 1.0000x reference)
#include <cuda_runtime.h>

#define IMG_H 512
#define IMG_W 512
#define NIMG  16
#define TW    32
#define TH    32
#define RW    42            // TW + 10 halo
#define RH    42            // TH + 10 halo
#define PSTR  43            // f32x2 stride, product arrays (odd -> fewer conflicts)
#define HSTR  33            // f32x2 stride, hblur arrays
#define NPIX  (NIMG * IMG_H * IMG_W)
#define NBLK  (NIMG * (IMG_H / TH) * (IMG_W / TW))   // 4096

typedef unsigned long long u64;

__device__ float g_part[NBLK];

// ---- packed f32x2 helpers (sm_100+ PTX; not emitted by ptxas from C++) ----
__device__ __forceinline__ u64 pk(float lo, float hi) {
    u64 r; asm("mov.b64 %0, {%1, %2};" : "=l"(r) : "f"(lo), "f"(hi)); return r;
}
__device__ __forceinline__ void upk(float& lo, float& hi, u64 v) {
    asm("mov.b64 {%0, %1}, %2;" : "=f"(lo), "=f"(hi) : "l"(v));
}
__device__ __forceinline__ u64 fma2(u64 a, u64 b, u64 c) {
    u64 d; asm("fma.rn.f32x2 %0, %1, %2, %3;" : "=l"(d) : "l"(a), "l"(b), "l"(c)); return d;
}

__global__ void __launch_bounds__(256, 2) ssim_main_kernel(
    const float* __restrict__ fused,
    const float* __restrict__ imga,
    const float* __restrict__ imgb)
{
    extern __shared__ u64 smem[];
    // products of raw pixels, packed: P0=(f,a) P1=(b,f2) P2=(a2,b2) P3=(fa,fb)
    u64* sP0 = smem;
    u64* sP1 = sP0 + RH * PSTR;
    u64* sP2 = sP1 + RH * PSTR;
    u64* sP3 = sP2 + RH * PSTR;
    // horizontally blurred channels, same packing
    u64* hb0 = sP3 + RH * PSTR;
    u64* hb1 = hb0 + RH * HSTR;
    u64* hb2 = hb1 + RH * HSTR;
    u64* hb3 = hb2 + RH * HSTR;

    constexpr float GW[11] = {
        0.00102838f, 0.00759876f, 0.03600077f, 0.10936069f, 0.21300553f,
        0.26601172f,
        0.21300553f, 0.10936069f, 0.03600077f, 0.00759876f, 0.00102838f};
    const float c1 = 0.0001f;   // 0.01^2
    const float c2 = 0.0009f;   // 0.03^2

    const int tid = threadIdx.x;
    const int gx0 = blockIdx.x * TW - 5;
    const int gy0 = blockIdx.y * TH - 5;
    const size_t base = (size_t)blockIdx.z * (IMG_H * IMG_W);
    const float* fP = fused + base;
    const float* aP = imga + base;
    const float* bP = imgb + base;

    // ---- Stage 0: load halo, normalize, form products ONCE per raw pixel ----
    // 48-wide stripes so warp lanes stay contiguous in x (coalesced LDG).
    for (int i = tid; i < RH * 48; i += 256) {
        int y = i / 48;
        int x = i - y * 48;
        if (x >= RW) continue;
        int gy = gy0 + y, gx = gx0 + x;
        float f = 0.f, a = 0.f, b = 0.f;
        if (gy >= 0 && gy < IMG_H && gx >= 0 && gx < IMG_W) {
            int g = gy * IMG_W + gx;
            f = (fP[g] + 1.f) * 0.5f;
            a = (aP[g] + 1.f) * 0.5f;
            b = (bP[g] + 1.f) * 0.5f;
        }
        int o = y * PSTR + x;
        sP0[o] = pk(f, a);
        sP1[o] = pk(b, f * f);
        sP2[o] = pk(a * a, b * b);
        sP3[o] = pk(f * a, f * b);
    }
    __syncthreads();

    // ---- Stage 1: horizontal 11-tap blur, 6 outputs/thread, packed fma2 ----
    // 42 rows x 6 groups = 252 tasks on 256 threads, single pass.
    if (tid < 252) {
        u64 W2[11];
#pragma unroll
        for (int k = 0; k < 11; k++) W2[k] = pk(GW[k], GW[k]);

        const int y  = tid / 6;
        const int g  = tid - y * 6;
        const int x0 = g * 6;                 // outputs x0..min(x0+5,31)
        const u64* r0 = sP0 + y * PSTR;
        const u64* r1 = sP1 + y * PSTR;
        const u64* r2 = sP2 + y * PSTR;
        const u64* r3 = sP3 + y * PSTR;

        u64 acc[6][4];
#pragma unroll
        for (int j = 0; j < 6; j++)
#pragma unroll
            for (int c = 0; c < 4; c++) acc[j][c] = 0ull;

#pragma unroll
        for (int k = 0; k < 16; k++) {
            int xr = x0 + k;
            u64 p0 = 0, p1 = 0, p2 = 0, p3 = 0;
            if (xr < RW) { p0 = r0[xr]; p1 = r1[xr]; p2 = r2[xr]; p3 = r3[xr]; }
#pragma unroll
            for (int j = 0; j < 6; j++) {
                int t = k - j;                // compile-time per (k,j)
                if (t >= 0 && t < 11) {
                    acc[j][0] = fma2(p0, W2[t], acc[j][0]);
                    acc[j][1] = fma2(p1, W2[t], acc[j][1]);
                    acc[j][2] = fma2(p2, W2[t], acc[j][2]);
                    acc[j][3] = fma2(p3, W2[t], acc[j][3]);
                }
            }
        }
#pragma unroll
        for (int j = 0; j < 6; j++) {
            int x = x0 + j;
            if (x < TW) {
                int o = y * HSTR + x;
                hb0[o] = acc[j][0];
                hb1[o] = acc[j][1];
                hb2[o] = acc[j][2];
                hb3[o] = acc[j][3];
            }
        }
    }
    __syncthreads();

    // ---- Stage 2: vertical blur, 4 outputs/thread, packed fma2 ----
    float lsum = 0.f;
    {
        u64 W2[11];
#pragma unroll
        for (int k = 0; k < 11; k++) W2[k] = pk(GW[k], GW[k]);

        const int x = tid & 31;
        const int ybase = (tid >> 5) * 4;

        u64 acc[4][4];
#pragma unroll
        for (int j = 0; j < 4; j++)
#pragma unroll
            for (int c = 0; c < 4; c++) acc[j][c] = 0ull;

#pragma unroll
        for (int r = 0; r < 14; r++) {
            int o = (ybase + r) * HSTR + x;
            u64 q0 = hb0[o], q1 = hb1[o], q2 = hb2[o], q3 = hb3[o];
#pragma unroll
            for (int j = 0; j < 4; j++) {
                int t = r - j;
                if (t >= 0 && t < 11) {
                    acc[j][0] = fma2(q0, W2[t], acc[j][0]);
                    acc[j][1] = fma2(q1, W2[t], acc[j][1]);
                    acc[j][2] = fma2(q2, W2[t], acc[j][2]);
                    acc[j][3] = fma2(q3, W2[t], acc[j][3]);
                }
            }
        }

        // ---- SSIM per pixel ----
#pragma unroll
        for (int j = 0; j < 4; j++) {
            float muF, muA, muB, eF2, eA2, eB2, eFA, eFB;
            upk(muF, muA, acc[j][0]);
            upk(muB, eF2, acc[j][1]);
            upk(eA2, eB2, acc[j][2]);
            upk(eFA, eFB, acc[j][3]);
            float muF2 = muF * muF;
            float sF2  = eF2 - muF2;
            {   // pair (fused, img_a)
                float mu22 = muA * muA;
                float mu12 = muF * muA;
                float s2v  = eA2 - mu22;
                float s12  = eFA - mu12;
                float num  = (2.f * mu12 + c1) * (2.f * s12 + c2);
                float den  = (muF2 + mu22 + c1) * (sF2 + s2v + c2);
                lsum += __fdividef(num, den);
            }
            {   // pair (fused, img_b)
                float mu22 = muB * muB;
                float mu12 = muF * muB;
                float s2v  = eB2 - mu22;
                float s12  = eFB - mu12;
                float num  = (2.f * mu12 + c1) * (2.f * s12 + c2);
                float den  = (muF2 + mu22 + c1) * (sF2 + s2v + c2);
                lsum += __fdividef(num, den);
            }
        }
    }

    // ---- Block reduction -> deterministic per-block partial ----
#pragma unroll
    for (int o = 16; o > 0; o >>= 1)
        lsum += __shfl_down_sync(0xffffffffu, lsum, o);

    __shared__ float wsum[8];
    if ((tid & 31) == 0) wsum[tid >> 5] = lsum;
    __syncthreads();
    if (tid < 8) {
        float v = wsum[tid];
        v += __shfl_down_sync(0xffu, v, 4);
        v += __shfl_down_sync(0xffu, v, 2);
        v += __shfl_down_sync(0xffu, v, 1);
        if (tid == 0) {
            int bi = ((int)blockIdx.z * gridDim.y + blockIdx.y) * gridDim.x
                     + blockIdx.x;
            g_part[bi] = v;
        }
    }
}

__global__ void __launch_bounds__(256) ssim_fin_kernel(float* __restrict__ out)
{
    int tid = threadIdx.x;
    float s = 0.f;
#pragma unroll
    for (int i = tid; i < NBLK; i += 256) s += g_part[i];

#pragma unroll
    for (int o = 16; o > 0; o >>= 1)
        s += __shfl_down_sync(0xffffffffu, s, o);

    __shared__ float wsum[8];
    if ((tid & 31) == 0) wsum[tid >> 5] = s;
    __syncthreads();
    if (tid == 0) {
        float tot = 0.f;
#pragma unroll
        for (int w = 0; w < 8; w++) tot += wsum[w];
        out[0] = (float)(1.0 - (double)tot / (2.0 * (double)NPIX));
    }
}

extern "C" void kernel_launch(void* const* d_in, const int* in_sizes, int n_in,
                              void* d_out, int out_size)
{
    (void)in_sizes; (void)n_in; (void)out_size;
    const float* fused = (const float*)d_in[0];
    const float* imga  = (const float*)d_in[1];
    const float* imgb  = (const float*)d_in[2];

    const size_t smem_bytes =
        (size_t)(4 * RH * PSTR + 4 * RH * HSTR) * sizeof(u64);  // ~102 KB
    cudaFuncSetAttribute(ssim_main_kernel,
                         cudaFuncAttributeMaxDynamicSharedMemorySize,
                         (int)smem_bytes);

    dim3 grid(IMG_W / TW, IMG_H / TH, NIMG);
    ssim_main_kernel<<<grid, 256, smem_bytes>>>(fused, imga, imgb);
    ssim_fin_kernel<<<1, 256>>>((float*)d_out);
}

// round 4
// speedup vs baseline: 1.2582x; 1.2582x over previous
#include <cuda_runtime.h>

#define IMG_H 512
#define IMG_W 512
#define NIMG  16
#define TW    32
#define TH    32
#define RW    42            // TW + 10 halo
#define RH    42            // TH + 10 halo
#define RSTR  45            // raw float stride: 45y mod 32 decorrelates banks
#define HSTR  33            // hblur u64 stride
#define NPIX  (NIMG * IMG_H * IMG_W)
#define NBLK  (NIMG * (IMG_H / TH) * (IMG_W / TW))   // 4096

typedef unsigned long long u64;

__device__ float        g_part[NBLK];
__device__ unsigned int g_count;     // zero-init at load; reset by last block

// ---- packed f32x2 helpers (sm_100+; ptxas never emits these from C++) ----
__device__ __forceinline__ u64 pk(float lo, float hi) {
    u64 r; asm("mov.b64 %0, {%1, %2};" : "=l"(r) : "f"(lo), "f"(hi)); return r;
}
__device__ __forceinline__ void upk(float& lo, float& hi, u64 v) {
    asm("mov.b64 {%0, %1}, %2;" : "=f"(lo), "=f"(hi) : "l"(v));
}
__device__ __forceinline__ u64 fma2(u64 a, u64 b, u64 c) {
    u64 d; asm("fma.rn.f32x2 %0, %1, %2, %3;" : "=l"(d) : "l"(a), "l"(b), "l"(c)); return d;
}
__device__ __forceinline__ u64 mul2(u64 a, u64 b) {
    u64 d; asm("mul.rn.f32x2 %0, %1, %2;" : "=l"(d) : "l"(a), "l"(b)); return d;
}

__global__ void __launch_bounds__(256) ssim_kernel(
    const float* __restrict__ fused,
    const float* __restrict__ imga,
    const float* __restrict__ imgb,
    float* __restrict__ out)
{
    extern __shared__ u64 smem[];
    // hblur channels first (u64-aligned): [4][RH][HSTR]
    u64* hb0 = smem;
    u64* hb1 = hb0 + RH * HSTR;
    u64* hb2 = hb1 + RH * HSTR;
    u64* hb3 = hb2 + RH * HSTR;
    // raw normalized images: [3][RH][RSTR] floats
    float* sF = (float*)(hb3 + RH * HSTR);
    float* sA = sF + RH * RSTR;
    float* sB = sA + RH * RSTR;

    constexpr float GW[11] = {
        0.00102838f, 0.00759876f, 0.03600077f, 0.10936069f, 0.21300553f,
        0.26601172f,
        0.21300553f, 0.10936069f, 0.03600077f, 0.00759876f, 0.00102838f};
    const float c1 = 0.0001f;   // 0.01^2
    const float c2 = 0.0009f;   // 0.03^2

    const int tid = threadIdx.x;
    const int gx0 = blockIdx.x * TW - 5;
    const int gy0 = blockIdx.y * TH - 5;
    const size_t base = (size_t)blockIdx.z * (IMG_H * IMG_W);
    const float* fP = fused + base;
    const float* aP = imga + base;
    const float* bP = imgb + base;

    // ---- Stage 0: load halo, normalize (x+1)/2, store raw channels ----
    for (int i = tid; i < RH * 48; i += 256) {
        int y = i / 48;
        int x = i - y * 48;
        if (x >= RW) continue;
        int gy = gy0 + y, gx = gx0 + x;
        float f = 0.f, a = 0.f, b = 0.f;
        if (gy >= 0 && gy < IMG_H && gx >= 0 && gx < IMG_W) {
            int g = gy * IMG_W + gx;
            f = fP[g] * 0.5f + 0.5f;
            a = aP[g] * 0.5f + 0.5f;
            b = bP[g] * 0.5f + 0.5f;
        }
        int o = y * RSTR + x;
        sF[o] = f;
        sA[o] = a;
        sB[o] = b;
    }
    __syncthreads();

    // ---- Stage 1: horizontal blur, sliding window of 4 outputs/thread ----
    // Products formed in REGISTERS per windowed pixel; only raw f,a,b read
    // from smem (12 B/pixel), packed accumulators kept in registers.
    {
        u64 W2[11];
#pragma unroll
        for (int k = 0; k < 11; k++) W2[k] = pk(GW[k], GW[k]);

        for (int i = tid; i < RH * 8; i += 256) {   // 336 tasks, 2 passes
            int y  = i >> 3;
            int x0 = (i & 7) * 4;                   // outputs x0..x0+3
            const float* fr = sF + y * RSTR + x0;
            const float* ar = sA + y * RSTR + x0;
            const float* br = sB + y * RSTR + x0;

            u64 acc[4][4];
#pragma unroll
            for (int j = 0; j < 4; j++)
#pragma unroll
                for (int c = 0; c < 4; c++) acc[j][c] = 0ull;

#pragma unroll
            for (int k = 0; k < 14; k++) {
                float f = fr[k], a = ar[k], b = br[k];
                u64 ab = pk(a, b);
                u64 P0 = pk(f, a);                  // (f , a )
                u64 P1 = pk(b, f * f);              // (b , f2)
                u64 P2 = mul2(ab, ab);              // (a2, b2)
                u64 P3 = mul2(pk(f, f), ab);        // (fa, fb)
#pragma unroll
                for (int j = 0; j < 4; j++) {
                    int t = k - j;                  // compile-time per (k,j)
                    if (t >= 0 && t < 11) {
                        acc[j][0] = fma2(P0, W2[t], acc[j][0]);
                        acc[j][1] = fma2(P1, W2[t], acc[j][1]);
                        acc[j][2] = fma2(P2, W2[t], acc[j][2]);
                        acc[j][3] = fma2(P3, W2[t], acc[j][3]);
                    }
                }
            }
#pragma unroll
            for (int j = 0; j < 4; j++) {
                int o = y * HSTR + x0 + j;
                hb0[o] = acc[j][0];
                hb1[o] = acc[j][1];
                hb2[o] = acc[j][2];
                hb3[o] = acc[j][3];
            }
        }
    }
    __syncthreads();

    // ---- Stage 2: vertical blur (4 outputs/thread) + SSIM ----
    float lsum = 0.f;
    {
        u64 W2[11];
#pragma unroll
        for (int k = 0; k < 11; k++) W2[k] = pk(GW[k], GW[k]);

        const int x = tid & 31;
        const int ybase = (tid >> 5) * 4;

        u64 acc[4][4];
#pragma unroll
        for (int j = 0; j < 4; j++)
#pragma unroll
            for (int c = 0; c < 4; c++) acc[j][c] = 0ull;

#pragma unroll
        for (int r = 0; r < 14; r++) {
            int o = (ybase + r) * HSTR + x;
            u64 q0 = hb0[o], q1 = hb1[o], q2 = hb2[o], q3 = hb3[o];
#pragma unroll
            for (int j = 0; j < 4; j++) {
                int t = r - j;
                if (t >= 0 && t < 11) {
                    acc[j][0] = fma2(q0, W2[t], acc[j][0]);
                    acc[j][1] = fma2(q1, W2[t], acc[j][1]);
                    acc[j][2] = fma2(q2, W2[t], acc[j][2]);
                    acc[j][3] = fma2(q3, W2[t], acc[j][3]);
                }
            }
        }

#pragma unroll
        for (int j = 0; j < 4; j++) {
            float muF, muA, muB, eF2, eA2, eB2, eFA, eFB;
            upk(muF, muA, acc[j][0]);
            upk(muB, eF2, acc[j][1]);
            upk(eA2, eB2, acc[j][2]);
            upk(eFA, eFB, acc[j][3]);
            float muF2 = muF * muF;
            float sF2  = eF2 - muF2;
            {   // pair (fused, img_a)
                float mu22 = muA * muA;
                float mu12 = muF * muA;
                float s2v  = eA2 - mu22;
                float s12  = eFA - mu12;
                float num  = (2.f * mu12 + c1) * (2.f * s12 + c2);
                float den  = (muF2 + mu22 + c1) * (sF2 + s2v + c2);
                lsum += __fdividef(num, den);
            }
            {   // pair (fused, img_b)
                float mu22 = muB * muB;
                float mu12 = muF * muB;
                float s2v  = eB2 - mu22;
                float s12  = eFB - mu12;
                float num  = (2.f * mu12 + c1) * (2.f * s12 + c2);
                float den  = (muF2 + mu22 + c1) * (sF2 + s2v + c2);
                lsum += __fdividef(num, den);
            }
        }
    }

    // ---- Block reduction -> deterministic per-block partial ----
#pragma unroll
    for (int o = 16; o > 0; o >>= 1)
        lsum += __shfl_down_sync(0xffffffffu, lsum, o);

    __shared__ float wsum[8];
    __shared__ bool  is_last;
    if ((tid & 31) == 0) wsum[tid >> 5] = lsum;
    __syncthreads();
    if (tid == 0) {
        float v = 0.f;
#pragma unroll
        for (int w = 0; w < 8; w++) v += wsum[w];
        int bi = ((int)blockIdx.z * gridDim.y + blockIdx.y) * gridDim.x
                 + blockIdx.x;
        g_part[bi] = v;
        __threadfence();
        unsigned prev = atomicAdd(&g_count, 1u);
        is_last = (prev == NBLK - 1);
    }
    __syncthreads();

    // ---- Last block: reduce all partials, write output, reset counter ----
    if (is_last) {
        double s = 0.0;
#pragma unroll
        for (int i = tid; i < NBLK; i += 256) s += (double)g_part[i];
#pragma unroll
        for (int o = 16; o > 0; o >>= 1)
            s += __shfl_down_sync(0xffffffffu, s, o);
        __shared__ double dsum[8];
        if ((tid & 31) == 0) dsum[tid >> 5] = s;
        __syncthreads();
        if (tid == 0) {
            double tot = 0.0;
#pragma unroll
            for (int w = 0; w < 8; w++) tot += dsum[w];
            out[0] = (float)(1.0 - tot / (2.0 * (double)NPIX));
            g_count = 0;      // reset for next graph replay
        }
    }
}

extern "C" void kernel_launch(void* const* d_in, const int* in_sizes, int n_in,
                              void* d_out, int out_size)
{
    (void)in_sizes; (void)n_in; (void)out_size;
    const float* fused = (const float*)d_in[0];
    const float* imga  = (const float*)d_in[1];
    const float* imgb  = (const float*)d_in[2];

    const size_t smem_bytes = (size_t)(4 * RH * HSTR) * sizeof(u64)
                            + (size_t)(3 * RH * RSTR) * sizeof(float); // ~67 KB
    cudaFuncSetAttribute(ssim_kernel,
                         cudaFuncAttributeMaxDynamicSharedMemorySize,
                         (int)smem_bytes);

    dim3 grid(IMG_W / TW, IMG_H / TH, NIMG);
    ssim_kernel<<<grid, 256, smem_bytes>>>(fused, imga, imgb, (float*)d_out);
}